// round 15
// baseline (speedup 1.0000x reference)
#include <cuda_runtime.h>
#include <cuda.h>
#include <cuda_bf16.h>
#include <math.h>
#include <stdint.h>

// ---------------------------------------------------------------------------
// AttentionBlock, bf16 mma.m16n8k16 + TMA. R15: BM=256 x BN=128 tiles
// (512 threads, warp grid 4x4) to cut L2->SMEM operand traffic 25%
// (LTS delivery cap ~42.6 B/cyc/SM identified as the binding limit).
// D[M,N] = alpha * A[M,K] . B[N,K]^T, bf16 in, fp32 accum.
// ---------------------------------------------------------------------------

static constexpr int BSZ  = 2;
static constexpr int CH   = 512;
static constexpr int NPIX = 4096;
static constexpr int NGRP = 32;
static constexpr int JT   = NPIX / 128;   // 32 j-tiles (QK grid.x)

typedef __nv_bfloat16 bf16;

__device__ bf16  g_hn[(size_t)BSZ * NPIX * CH];          // hnT [b][n][c]
__device__ bf16  g_qk[(size_t)BSZ * NPIX * 2 * CH];      // qkT [b][n][1024]
__device__ bf16  g_v [(size_t)BSZ * CH * NPIX];          // v   [b][c][n]
__device__ bf16  g_o [(size_t)BSZ * NPIX * CH];          // oT  [b][n][c]
__device__ bf16  g_p [(size_t)BSZ * NPIX * NPIX];        // p~ = exp(logit)
__device__ float g_psum[(size_t)BSZ * NPIX * JT];
__device__ float g_inv [(size_t)BSZ * NPIX];
__device__ bf16  g_wqk[2 * CH * CH];
__device__ bf16  g_wv[CH * CH];
__device__ bf16  g_wp[CH * CH];
__device__ float g_bqk[2 * CH];
__device__ float g_pstats[BSZ * NGRP * 8 * 2];           // phase-1 partials
__device__ float g_stats[BSZ * NGRP * 2];

// ---------------------------------------------------------------------------
__device__ __forceinline__ uint32_t smem_u32(const void* p) {
    return (uint32_t)__cvta_generic_to_shared(p);
}
__device__ __forceinline__ uint32_t swz(uint32_t off) {
    return off ^ ((off >> 3) & 0x70);
}
__device__ __forceinline__ void mbar_init(uint32_t a, uint32_t cnt) {
    asm volatile("mbarrier.init.shared.b64 [%0], %1;" :: "r"(a), "r"(cnt) : "memory");
}
__device__ __forceinline__ void mbar_arrive(uint32_t a) {
    asm volatile("mbarrier.arrive.shared.b64 _, [%0];" :: "r"(a) : "memory");
}
__device__ __forceinline__ void mbar_expect_tx(uint32_t a, uint32_t bytes) {
    asm volatile("mbarrier.arrive.expect_tx.shared.b64 _, [%0], %1;"
                 :: "r"(a), "r"(bytes) : "memory");
}
__device__ __forceinline__ void mbar_wait(uint32_t a, uint32_t parity) {
    asm volatile(
        "{\n\t.reg .pred P;\n\t"
        "W_%=:\n\t"
        "mbarrier.try_wait.parity.acquire.cta.shared::cta.b64 P, [%0], %1, 0x989680;\n\t"
        "@!P bra W_%=;\n\t}"
        :: "r"(a), "r"(parity) : "memory");
}
__device__ __forceinline__ void tma_load3d(uint32_t dst, const CUtensorMap* tm,
                                           int x, int y, int z, uint32_t mbar) {
    asm volatile(
        "cp.async.bulk.tensor.3d.shared::cta.global.tile.mbarrier::complete_tx::bytes "
        "[%0], [%1, {%2, %3, %4}], [%5];"
        :: "r"(dst), "l"(tm), "r"(x), "r"(y), "r"(z), "r"(mbar) : "memory");
}
__device__ __forceinline__ void ldsm_x4(uint32_t& r0, uint32_t& r1,
                                        uint32_t& r2, uint32_t& r3, uint32_t a) {
    asm volatile("ldmatrix.sync.aligned.m8n8.x4.shared.b16 {%0,%1,%2,%3}, [%4];"
                 : "=r"(r0), "=r"(r1), "=r"(r2), "=r"(r3) : "r"(a));
}
__device__ __forceinline__ void mma_bf16(float* c, const uint32_t* a, const uint32_t* b) {
    asm volatile(
        "mma.sync.aligned.m16n8k16.row.col.f32.bf16.bf16.f32 "
        "{%0,%1,%2,%3}, {%4,%5,%6,%7}, {%8,%9}, {%0,%1,%2,%3};"
        : "+f"(c[0]), "+f"(c[1]), "+f"(c[2]), "+f"(c[3])
        : "r"(a[0]), "r"(a[1]), "r"(a[2]), "r"(a[3]), "r"(b[0]), "r"(b[1]));
}

// ---------------------------------------------------------------------------
// prep kernels
// ---------------------------------------------------------------------------
__global__ void round_weights_kernel(const float* __restrict__ a, const float* __restrict__ b,
                                     const float* __restrict__ c, const float* __restrict__ d,
                                     bf16* __restrict__ wqk, bf16* __restrict__ wv,
                                     bf16* __restrict__ wp)
{
    int i = blockIdx.x * blockDim.x + threadIdx.x;
    int w = i >> 18;
    int off = i & ((1 << 18) - 1);
    const float* src = (w == 0) ? a : (w == 1) ? b : (w == 2) ? c : d;
    bf16* dst = (w == 0) ? wqk : (w == 1) ? (wqk + CH * CH) : (w == 2) ? wv : wp;
    dst[off] = __float2bfloat16_rn(src[off]);
}
__global__ void bias_concat_kernel(const float* __restrict__ bq,
                                   const float* __restrict__ bk,
                                   float* __restrict__ o)
{
    int i = blockIdx.x * blockDim.x + threadIdx.x;
    o[i] = (i < CH) ? bq[i] : bk[i - CH];
}

// GroupNorm stats phase 1: 8 blocks per (b,g), partial sums.
__global__ void gn_stats1_kernel(const float* __restrict__ x, float* __restrict__ pstats)
{
    const int CHUNK = 8192;                  // floats per block
    const float4* xp = (const float4*)(x + (size_t)blockIdx.x * CHUNK);
    float s = 0.f, ss = 0.f;
    #pragma unroll
    for (int i = 0; i < CHUNK / 4 / 256; i++) {
        float4 v = xp[i * 256 + threadIdx.x];
        s  += v.x + v.y + v.z + v.w;
        ss += v.x * v.x + v.y * v.y + v.z * v.z + v.w * v.w;
    }
    __shared__ float sh[16];
    #pragma unroll
    for (int o = 16; o; o >>= 1) {
        s  += __shfl_xor_sync(0xffffffffu, s,  o);
        ss += __shfl_xor_sync(0xffffffffu, ss, o);
    }
    int wid = threadIdx.x >> 5, lid = threadIdx.x & 31;
    if (lid == 0) { sh[wid] = s; sh[8 + wid] = ss; }
    __syncthreads();
    if (threadIdx.x == 0) {
        s = 0.f; ss = 0.f;
        #pragma unroll
        for (int w = 0; w < 8; w++) { s += sh[w]; ss += sh[8 + w]; }
        pstats[blockIdx.x * 2 + 0] = s;
        pstats[blockIdx.x * 2 + 1] = ss;
    }
}
// phase 2: finalize 64 groups
__global__ void gn_stats2_kernel(const float* __restrict__ pstats, float* __restrict__ stats)
{
    int g = threadIdx.x;                     // 0..63
    if (g < BSZ * NGRP) {
        float s = 0.f, ss = 0.f;
        #pragma unroll
        for (int j = 0; j < 8; j++) {
            s  += pstats[(g * 8 + j) * 2 + 0];
            ss += pstats[(g * 8 + j) * 2 + 1];
        }
        const float NPG = (float)((CH / NGRP) * NPIX);
        float mean = s / NPG;
        float var  = ss / NPG - mean * mean;
        stats[g * 2 + 0] = mean;
        stats[g * 2 + 1] = rsqrtf(var + 1e-6f);
    }
}

// Normalize + transpose: x[b][c][n] -> hnT[b][n][c] bf16. Tile 32c x 128n.
__global__ void __launch_bounds__(256)
gn_transpose_kernel(const float* __restrict__ x, const float* __restrict__ stats,
                    const float* __restrict__ scale, const float* __restrict__ bias,
                    bf16* __restrict__ hnT)
{
    __shared__ float tile[32 * 132];
    const int n0 = blockIdx.x * 128;
    const int c0 = blockIdx.y * 32;
    const int b  = blockIdx.z;
    const float* xb = x + (size_t)b * CH * NPIX;
    bf16* hb = hnT + (size_t)b * NPIX * CH;
    const int tid = threadIdx.x;

    #pragma unroll
    for (int r = 0; r < 4; r++) {
        int idx = r * 256 + tid;
        int ci  = idx >> 5;
        int n4  = idx & 31;
        int c   = c0 + ci;
        int g   = c >> 4;
        float mean = stats[(b * NGRP + g) * 2 + 0];
        float rstd = stats[(b * NGRP + g) * 2 + 1];
        float sc = scale[c], bi = bias[c];
        float4 v = *(const float4*)&xb[(size_t)c * NPIX + n0 + n4 * 4];
        float* tp = &tile[ci * 132 + n4 * 4];
        tp[0] = (v.x - mean) * rstd * sc + bi;
        tp[1] = (v.y - mean) * rstd * sc + bi;
        tp[2] = (v.z - mean) * rstd * sc + bi;
        tp[3] = (v.w - mean) * rstd * sc + bi;
    }
    __syncthreads();
    #pragma unroll
    for (int r = 0; r < 2; r++) {
        int idx = r * 256 + tid;
        int ni  = idx >> 2;
        int cq  = idx & 3;
        uint32_t w[4];
        #pragma unroll
        for (int j = 0; j < 4; j++) {
            float lo = tile[(cq * 8 + 2 * j)     * 132 + ni];
            float hi = tile[(cq * 8 + 2 * j + 1) * 132 + ni];
            __nv_bfloat162 p;
            p.x = __float2bfloat16_rn(lo);
            p.y = __float2bfloat16_rn(hi);
            w[j] = *(uint32_t*)&p;
        }
        *(uint4*)&hb[(size_t)(n0 + ni) * CH + c0 + cq * 8] = *(uint4*)w;
    }
}

__global__ void rowsum_inv_kernel(const float* __restrict__ psum, float* __restrict__ inv)
{
    int i = blockIdx.x * blockDim.x + threadIdx.x;
    const float* p = psum + (size_t)i * JT;
    float s = 0.f;
    #pragma unroll
    for (int j = 0; j < JT; j++) s += p[j];
    inv[i] = 1.f / s;
}

// ---------------------------------------------------------------------------
// TMA-fed bf16 GEMM. BM=256, BN=128, BK=64 (SW128), 3 stages, 512 threads,
// warp grid 4x4 (warp tile 64x32), m16n8k16, full/empty mbarrier pipeline.
// BIAS_MODE: 0 none, 1 bias[m], 2 bias[n], 3 softmax epi (exp + psum),
//            4 rowscale (bias = inv[b*NPIX+m]).  BA/BB: operand batched.
// ---------------------------------------------------------------------------
static constexpr int A_TILE  = 256 * 128;            // 32KB
static constexpr int B_TILE  = 128 * 128;            // 16KB
static constexpr int STAGE_B = A_TILE + B_TILE;      // 48KB
static constexpr int GSMEM   = 1024 + 3 * STAGE_B + 128;

template <int BIAS_MODE, bool RES, bool OUT_BF, bool BA, bool BB>
__global__ void __launch_bounds__(512)
tgemm(int nt, int kAo, int kBo,
      const __grid_constant__ CUtensorMap tmA,
      const __grid_constant__ CUtensorMap tmB,
      void* __restrict__ Cvp, int ldc, size_t sC,
      const float* __restrict__ bias,
      const float* __restrict__ res, size_t sR,
      float alpha)
{
    extern __shared__ char smraw[];
    const uint32_t sb = smem_u32(smraw);
    const uint32_t tb = (sb + 1023) & ~1023u;
    const uint32_t fullb  = tb + 3 * STAGE_B;
    const uint32_t emptyb = fullb + 24;

    const int bz = blockIdx.z;
    const int m0 = blockIdx.y * 256;
    const int n0 = blockIdx.x * 128;
    const int tid  = threadIdx.x;
    const int lane = tid & 31;
    const int wid  = tid >> 5;
    const int wm   = wid >> 2;        // 0..3 -> 64 rows each
    const int wn   = wid & 3;         // 0..3 -> 32 cols each
    const int grp  = lane >> 2;
    const int tig  = lane & 3;
    const int lrow = lane & 15;
    const int lkb  = (lane >> 4) << 4;
    const int zA = BA ? bz : 0;
    const int zB = BB ? bz : 0;

    if (RES) res += sR * bz;

    if (tid == 0) {
        #pragma unroll
        for (int s = 0; s < 3; s++) {
            mbar_init(fullb  + 8 * s, 1);
            mbar_init(emptyb + 8 * s, 16);
        }
    }
    __syncthreads();

    if (tid == 0) {
        #pragma unroll
        for (int s = 0; s < 3; s++) {
            mbar_expect_tx(fullb + 8 * s, STAGE_B);
            tma_load3d(tb + s * STAGE_B,          &tmA, kAo + s * 64, m0, zA, fullb + 8 * s);
            tma_load3d(tb + s * STAGE_B + A_TILE, &tmB, kBo + s * 64, n0, zB, fullb + 8 * s);
        }
    }

    float acc[4][4][4];
    #pragma unroll
    for (int mi = 0; mi < 4; mi++)
        #pragma unroll
        for (int ni = 0; ni < 4; ni++)
            #pragma unroll
            for (int r = 0; r < 4; r++)
                acc[mi][ni][r] = 0.f;

    for (int t = 0; t < nt; t++) {
        const int tp = t / 3;
        const int st = t - tp * 3;
        const uint32_t ph = tp & 1;
        mbar_wait(fullb + 8 * st, ph);
        const uint32_t As = tb + st * STAGE_B;
        const uint32_t Bs = As + A_TILE;

        #pragma unroll
        for (int ks = 0; ks < 4; ks++) {
            const uint32_t colb = ks * 32 + lkb;
            uint32_t af[4][4];
            #pragma unroll
            for (int mi = 0; mi < 4; mi++) {
                int row = wm * 64 + mi * 16 + lrow;
                ldsm_x4(af[mi][0], af[mi][1], af[mi][2], af[mi][3],
                        As + swz(row * 128 + colb));
            }
            uint32_t bfr[4][2];
            #pragma unroll
            for (int nb = 0; nb < 2; nb++) {
                int row = wn * 32 + nb * 16 + lrow;
                uint32_t r0, r1, r2, r3;
                ldsm_x4(r0, r1, r2, r3, Bs + swz(row * 128 + colb));
                bfr[nb * 2][0] = r0; bfr[nb * 2][1] = r2;
                bfr[nb * 2 + 1][0] = r1; bfr[nb * 2 + 1][1] = r3;
            }
            #pragma unroll
            for (int mi = 0; mi < 4; mi++)
                #pragma unroll
                for (int ni = 0; ni < 4; ni++)
                    mma_bf16(acc[mi][ni], af[mi], bfr[ni]);
        }
        if (lane == 0) mbar_arrive(emptyb + 8 * st);
        if (tid == 0 && t + 3 < nt) {
            mbar_wait(emptyb + 8 * st, ph);
            mbar_expect_tx(fullb + 8 * st, STAGE_B);
            tma_load3d(tb + st * STAGE_B,          &tmA, kAo + (t + 3) * 64, m0, zA, fullb + 8 * st);
            tma_load3d(tb + st * STAGE_B + A_TILE, &tmB, kBo + (t + 3) * 64, n0, zB, fullb + 8 * st);
        }
    }

    // -------------------- epilogue --------------------
    float* rows_s = (float*)smraw;     // [4][256] partials (mode 3); tiles dead
    if (BIAS_MODE == 3) __syncthreads();

    #pragma unroll
    for (int mi = 0; mi < 4; mi++) {
        int lr0 = wm * 64 + mi * 16 + grp;
        int r0 = m0 + lr0;
        int r1 = r0 + 8;
        float brow0 = (BIAS_MODE == 1) ? bias[r0] : 0.f;
        float brow1 = (BIAS_MODE == 1) ? bias[r1] : 0.f;
        float sc0 = 1.f, sc1 = 1.f;
        if (BIAS_MODE == 4) {
            sc0 = bias[(size_t)bz * NPIX + r0];
            sc1 = bias[(size_t)bz * NPIX + r1];
        }
        float rsum0 = 0.f, rsum1 = 0.f;
        #pragma unroll
        for (int ni = 0; ni < 4; ni++) {
            int c = n0 + wn * 32 + ni * 8 + tig * 2;
            float v0 = acc[mi][ni][0] * alpha;
            float v1 = acc[mi][ni][1] * alpha;
            float v2 = acc[mi][ni][2] * alpha;
            float v3 = acc[mi][ni][3] * alpha;
            if (BIAS_MODE == 1) { v0 += brow0; v1 += brow0; v2 += brow1; v3 += brow1; }
            if (BIAS_MODE == 2) {
                float bc0 = bias[c], bc1 = bias[c + 1];
                v0 += bc0; v1 += bc1; v2 += bc0; v3 += bc1;
            }
            if (BIAS_MODE == 3) {
                v0 = __expf(v0); v1 = __expf(v1);
                v2 = __expf(v2); v3 = __expf(v3);
                rsum0 += v0 + v1; rsum1 += v2 + v3;
            }
            if (BIAS_MODE == 4) { v0 *= sc0; v1 *= sc0; v2 *= sc1; v3 *= sc1; }
            if (RES) {
                v0 += res[(size_t)r0 * ldc + c];
                v1 += res[(size_t)r0 * ldc + c + 1];
                v2 += res[(size_t)r1 * ldc + c];
                v3 += res[(size_t)r1 * ldc + c + 1];
            }
            if (OUT_BF) {
                bf16* Cp = (bf16*)Cvp + sC * bz;
                __nv_bfloat162 w0, w1;
                w0.x = __float2bfloat16_rn(v0); w0.y = __float2bfloat16_rn(v1);
                w1.x = __float2bfloat16_rn(v2); w1.y = __float2bfloat16_rn(v3);
                *(__nv_bfloat162*)&Cp[(size_t)r0 * ldc + c] = w0;
                *(__nv_bfloat162*)&Cp[(size_t)r1 * ldc + c] = w1;
            } else {
                float* Cp = (float*)Cvp + sC * bz;
                *(float2*)&Cp[(size_t)r0 * ldc + c] = make_float2(v0, v1);
                *(float2*)&Cp[(size_t)r1 * ldc + c] = make_float2(v2, v3);
            }
        }
        if (BIAS_MODE == 3) {
            // sum the 4 tig lanes (exact: commutative tree within quad)
            rsum0 += __shfl_xor_sync(0xffffffffu, rsum0, 1);
            rsum0 += __shfl_xor_sync(0xffffffffu, rsum0, 2);
            rsum1 += __shfl_xor_sync(0xffffffffu, rsum1, 1);
            rsum1 += __shfl_xor_sync(0xffffffffu, rsum1, 2);
            if (tig == 0) {                       // unique (wn,row) writer
                rows_s[wn * 256 + lr0]     = rsum0;
                rows_s[wn * 256 + lr0 + 8] = rsum1;
            }
        }
    }
    if (BIAS_MODE == 3) {
        __syncthreads();
        if (tid < 256) {
            float s = 0.f;
            #pragma unroll
            for (int w = 0; w < 4; w++) s += rows_s[w * 256 + tid];   // fixed order
            float* psum = (float*)bias;
            psum[((size_t)bz * NPIX + m0 + tid) * JT + blockIdx.x] = s;
        }
    }
}

// ---------------------------------------------------------------------------
// Launch
// ---------------------------------------------------------------------------
typedef CUresult (*EncodeFn)(CUtensorMap*, CUtensorMapDataType, cuuint32_t, void*,
                             const cuuint64_t*, const cuuint64_t*, const cuuint32_t*,
                             const cuuint32_t*, CUtensorMapInterleave, CUtensorMapSwizzle,
                             CUtensorMapL2promotion, CUtensorMapFloatOOBfill);

static void encode3d(EncodeFn fn, CUtensorMap* tm, void* ptr,
                     uint64_t d0, uint64_t d1, uint64_t d2,
                     uint64_t s1_bytes, uint64_t s2_bytes, uint32_t box1)
{
    cuuint64_t dims[3]    = {d0, d1, d2};
    cuuint64_t strides[2] = {s1_bytes, s2_bytes};
    cuuint32_t box[3]     = {64, box1, 1};
    cuuint32_t es[3]      = {1, 1, 1};
    fn(tm, CU_TENSOR_MAP_DATA_TYPE_BFLOAT16, 3, ptr, dims, strides, box, es,
       CU_TENSOR_MAP_INTERLEAVE_NONE, CU_TENSOR_MAP_SWIZZLE_128B,
       CU_TENSOR_MAP_L2_PROMOTION_L2_128B, CU_TENSOR_MAP_FLOAT_OOB_FILL_NONE);
}

extern "C" void kernel_launch(void* const* d_in, const int* in_sizes, int n_in,
                              void* d_out, int out_size)
{
    const float* x        = (const float*)d_in[0];
    const float* gn_scale = (const float*)d_in[1];
    const float* gn_bias  = (const float*)d_in[2];
    const float* wq       = (const float*)d_in[3];
    const float* bq       = (const float*)d_in[4];
    const float* wk       = (const float*)d_in[5];
    const float* bk       = (const float*)d_in[6];
    const float* wv       = (const float*)d_in[7];
    const float* bv       = (const float*)d_in[8];
    const float* wp       = (const float*)d_in[9];
    const float* bp       = (const float*)d_in[10];
    float* out            = (float*)d_out;

    static bf16 *hnT = nullptr, *qkT, *v, *probs, *oT, *rwqk, *rwv, *rwp;
    static float *stats, *pstats, *bqk, *psum, *inv;
    static CUtensorMap tmHN_A, tmHN_B, tmWQK_B, tmWV_A, tmQK_A, tmQK_B,
                       tmP_A, tmV_B, tmWP_A, tmO_B;
    if (!hnT) {
        cudaGetSymbolAddress((void**)&hnT,  g_hn);
        cudaGetSymbolAddress((void**)&qkT,  g_qk);
        cudaGetSymbolAddress((void**)&v,    g_v);
        cudaGetSymbolAddress((void**)&probs,g_p);
        cudaGetSymbolAddress((void**)&oT,   g_o);
        cudaGetSymbolAddress((void**)&rwqk, g_wqk);
        cudaGetSymbolAddress((void**)&rwv,  g_wv);
        cudaGetSymbolAddress((void**)&rwp,  g_wp);
        cudaGetSymbolAddress((void**)&bqk,  g_bqk);
        cudaGetSymbolAddress((void**)&stats, g_stats);
        cudaGetSymbolAddress((void**)&pstats, g_pstats);
        cudaGetSymbolAddress((void**)&psum, g_psum);
        cudaGetSymbolAddress((void**)&inv,  g_inv);

        void* fp = nullptr;
        cudaDriverEntryPointQueryResult qr;
        cudaGetDriverEntryPoint("cuTensorMapEncodeTiled", &fp, cudaEnableDefault, &qr);
        EncodeFn enc = (EncodeFn)fp;

        const uint64_t sCNb = (uint64_t)CH * NPIX * 2;
        const uint64_t sNNb = (uint64_t)NPIX * NPIX * 2;
        const uint64_t sQKb = (uint64_t)NPIX * 2 * CH * 2;
        encode3d(enc, &tmHN_A,  hnT,  CH,     NPIX, BSZ, CH * 2,     sCNb, 256);
        encode3d(enc, &tmHN_B,  hnT,  CH,     NPIX, BSZ, CH * 2,     sCNb, 128);
        encode3d(enc, &tmWQK_B, rwqk, CH,     1024, 1,   CH * 2,     (uint64_t)1024 * CH * 2, 128);
        encode3d(enc, &tmWV_A,  rwv,  CH,     CH,   1,   CH * 2,     (uint64_t)CH * CH * 2, 256);
        encode3d(enc, &tmQK_A,  qkT,  2 * CH, NPIX, BSZ, 2 * CH * 2, sQKb, 256);
        encode3d(enc, &tmQK_B,  qkT,  2 * CH, NPIX, BSZ, 2 * CH * 2, sQKb, 128);
        encode3d(enc, &tmP_A,   probs,NPIX,   NPIX, BSZ, NPIX * 2,   sNNb, 256);
        encode3d(enc, &tmV_B,   v,    NPIX,   CH,   BSZ, NPIX * 2,   sCNb, 128);
        encode3d(enc, &tmWP_A,  rwp,  CH,     CH,   1,   CH * 2,     (uint64_t)CH * CH * 2, 256);
        encode3d(enc, &tmO_B,   oT,   CH,     NPIX, BSZ, CH * 2,     sCNb, 128);

        cudaFuncSetAttribute(tgemm<2, false, true,  true,  false>,
                             cudaFuncAttributeMaxDynamicSharedMemorySize, GSMEM);
        cudaFuncSetAttribute(tgemm<1, false, true,  false, true >,
                             cudaFuncAttributeMaxDynamicSharedMemorySize, GSMEM);
        cudaFuncSetAttribute(tgemm<3, false, true,  true,  true >,
                             cudaFuncAttributeMaxDynamicSharedMemorySize, GSMEM);
        cudaFuncSetAttribute(tgemm<4, false, true,  true,  true >,
                             cudaFuncAttributeMaxDynamicSharedMemorySize, GSMEM);
        cudaFuncSetAttribute(tgemm<1, true,  false, false, true >,
                             cudaFuncAttributeMaxDynamicSharedMemorySize, GSMEM);
    }

    const size_t sCN = (size_t)CH * NPIX;
    const size_t sNN = (size_t)NPIX * NPIX;
    const size_t sQK = (size_t)NPIX * 2 * CH;
    const float inv_sqrt_c = 0.044194173824159216f;

    round_weights_kernel<<<4 * CH * CH / 256, 256>>>(wq, wk, wv, wp, rwqk, rwv, rwp);
    bias_concat_kernel<<<4, 256>>>(bq, bk, bqk);
    gn_stats1_kernel<<<BSZ * NGRP * 8, 256>>>(x, pstats);
    gn_stats2_kernel<<<1, 64>>>(pstats, stats);
    gn_transpose_kernel<<<dim3(NPIX / 128, CH / 32, BSZ), 256>>>(x, stats, gn_scale, gn_bias, hnT);

    // qkT = hnT . Wqk^T + bqk   (M=4096, N=1024, K=512)
    tgemm<2, false, true, true, false><<<dim3(8, 16, BSZ), 512, GSMEM>>>(
        8, 0, 0, tmHN_A, tmWQK_B, qkT, 2 * CH, sQK, bqk, nullptr, 0, 1.f);

    // v = Wv . hnT^T + bv   (M=512, N=4096, K=512)
    tgemm<1, false, true, false, true><<<dim3(32, 2, BSZ), 512, GSMEM>>>(
        8, 0, 0, tmWV_A, tmHN_B, v, NPIX, sCN, bv, nullptr, 0, 1.f);

    // p~ = exp(alpha * q . k^T)   (M=N=4096, K=512)
    tgemm<3, false, true, true, true><<<dim3(32, 16, BSZ), 512, GSMEM>>>(
        8, 0, 512, tmQK_A, tmQK_B, probs, NPIX, sNN, psum, nullptr, 0, inv_sqrt_c);

    rowsum_inv_kernel<<<BSZ * NPIX / 256, 256>>>(psum, inv);

    // oT = diag(inv) . p~ . v^T   (M=4096, N=512, K=4096)
    tgemm<4, false, true, true, true><<<dim3(4, 16, BSZ), 512, GSMEM>>>(
        64, 0, 0, tmP_A, tmV_B, oT, CH, sCN, inv, nullptr, 0, 1.f);

    // out = Wp . oT^T + bp + x   (M=512, N=4096, K=512)
    tgemm<1, true, false, false, true><<<dim3(32, 2, BSZ), 512, GSMEM>>>(
        8, 0, 0, tmWP_A, tmO_B, out, NPIX, sCN, bp, x, sCN, 1.f);
}

// round 16
// speedup vs baseline: 1.0275x; 1.0275x over previous
#include <cuda_runtime.h>
#include <cuda.h>
#include <cuda_bf16.h>
#include <math.h>
#include <stdint.h>

// ---------------------------------------------------------------------------
// AttentionBlock, bf16 mma.m16n8k16 + TMA (R14 GEMM core), fused prep:
// stats2 -> gn_transpose, bias_concat -> round_weights, rowsum_inv -> AV epi.
// D[M,N] = alpha * A[M,K] . B[N,K]^T, bf16 in, fp32 accum.
// ---------------------------------------------------------------------------

static constexpr int BSZ  = 2;
static constexpr int CH   = 512;
static constexpr int NPIX = 4096;
static constexpr int NGRP = 32;
static constexpr int JT   = NPIX / 128;   // 32 j-tiles per row

typedef __nv_bfloat16 bf16;

__device__ bf16  g_hn[(size_t)BSZ * NPIX * CH];          // hnT [b][n][c]
__device__ bf16  g_qk[(size_t)BSZ * NPIX * 2 * CH];      // qkT [b][n][1024]
__device__ bf16  g_v [(size_t)BSZ * CH * NPIX];          // v   [b][c][n]
__device__ bf16  g_o [(size_t)BSZ * NPIX * CH];          // oT  [b][n][c]
__device__ bf16  g_p [(size_t)BSZ * NPIX * NPIX];        // p~ = exp(logit)
__device__ float g_psum[(size_t)BSZ * NPIX * JT];
__device__ bf16  g_wqk[2 * CH * CH];
__device__ bf16  g_wv[CH * CH];
__device__ bf16  g_wp[CH * CH];
__device__ float g_bqk[2 * CH];
__device__ float g_pstats[BSZ * NGRP * 8 * 2];           // phase-1 partials

// ---------------------------------------------------------------------------
__device__ __forceinline__ uint32_t smem_u32(const void* p) {
    return (uint32_t)__cvta_generic_to_shared(p);
}
__device__ __forceinline__ uint32_t swz(uint32_t off) {
    return off ^ ((off >> 3) & 0x70);
}
__device__ __forceinline__ void mbar_init(uint32_t a, uint32_t cnt) {
    asm volatile("mbarrier.init.shared.b64 [%0], %1;" :: "r"(a), "r"(cnt) : "memory");
}
__device__ __forceinline__ void mbar_arrive(uint32_t a) {
    asm volatile("mbarrier.arrive.shared.b64 _, [%0];" :: "r"(a) : "memory");
}
__device__ __forceinline__ void mbar_expect_tx(uint32_t a, uint32_t bytes) {
    asm volatile("mbarrier.arrive.expect_tx.shared.b64 _, [%0], %1;"
                 :: "r"(a), "r"(bytes) : "memory");
}
__device__ __forceinline__ void mbar_wait(uint32_t a, uint32_t parity) {
    asm volatile(
        "{\n\t.reg .pred P;\n\t"
        "W_%=:\n\t"
        "mbarrier.try_wait.parity.acquire.cta.shared::cta.b64 P, [%0], %1, 0x989680;\n\t"
        "@!P bra W_%=;\n\t}"
        :: "r"(a), "r"(parity) : "memory");
}
__device__ __forceinline__ void tma_load3d(uint32_t dst, const CUtensorMap* tm,
                                           int x, int y, int z, uint32_t mbar) {
    asm volatile(
        "cp.async.bulk.tensor.3d.shared::cta.global.tile.mbarrier::complete_tx::bytes "
        "[%0], [%1, {%2, %3, %4}], [%5];"
        :: "r"(dst), "l"(tm), "r"(x), "r"(y), "r"(z), "r"(mbar) : "memory");
}
__device__ __forceinline__ void ldsm_x4(uint32_t& r0, uint32_t& r1,
                                        uint32_t& r2, uint32_t& r3, uint32_t a) {
    asm volatile("ldmatrix.sync.aligned.m8n8.x4.shared.b16 {%0,%1,%2,%3}, [%4];"
                 : "=r"(r0), "=r"(r1), "=r"(r2), "=r"(r3) : "r"(a));
}
__device__ __forceinline__ void mma_bf16(float* c, const uint32_t* a, const uint32_t* b) {
    asm volatile(
        "mma.sync.aligned.m16n8k16.row.col.f32.bf16.bf16.f32 "
        "{%0,%1,%2,%3}, {%4,%5,%6,%7}, {%8,%9}, {%0,%1,%2,%3};"
        : "+f"(c[0]), "+f"(c[1]), "+f"(c[2]), "+f"(c[3])
        : "r"(a[0]), "r"(a[1]), "r"(a[2]), "r"(a[3]), "r"(b[0]), "r"(b[1]));
}

// ---------------------------------------------------------------------------
// prep: weights -> bf16 + bias concat (fused)
// ---------------------------------------------------------------------------
__global__ void round_weights_kernel(const float* __restrict__ a, const float* __restrict__ b,
                                     const float* __restrict__ c, const float* __restrict__ d,
                                     bf16* __restrict__ wqk, bf16* __restrict__ wv,
                                     bf16* __restrict__ wp,
                                     const float* __restrict__ bq,
                                     const float* __restrict__ bk,
                                     float* __restrict__ bqk)
{
    int i = blockIdx.x * blockDim.x + threadIdx.x;
    int w = i >> 18;
    int off = i & ((1 << 18) - 1);
    const float* src = (w == 0) ? a : (w == 1) ? b : (w == 2) ? c : d;
    bf16* dst = (w == 0) ? wqk : (w == 1) ? (wqk + CH * CH) : (w == 2) ? wv : wp;
    dst[off] = __float2bfloat16_rn(src[off]);
    if (i < 2 * CH) bqk[i] = (i < CH) ? bq[i] : bk[i - CH];
}

// GroupNorm stats phase 1: 8 blocks per (b,g), partial sums.
__global__ void gn_stats1_kernel(const float* __restrict__ x, float* __restrict__ pstats)
{
    const int CHUNK = 8192;
    const float4* xp = (const float4*)(x + (size_t)blockIdx.x * CHUNK);
    float s = 0.f, ss = 0.f;
    #pragma unroll
    for (int i = 0; i < CHUNK / 4 / 256; i++) {
        float4 v = xp[i * 256 + threadIdx.x];
        s  += v.x + v.y + v.z + v.w;
        ss += v.x * v.x + v.y * v.y + v.z * v.z + v.w * v.w;
    }
    __shared__ float sh[16];
    #pragma unroll
    for (int o = 16; o; o >>= 1) {
        s  += __shfl_xor_sync(0xffffffffu, s,  o);
        ss += __shfl_xor_sync(0xffffffffu, ss, o);
    }
    int wid = threadIdx.x >> 5, lid = threadIdx.x & 31;
    if (lid == 0) { sh[wid] = s; sh[8 + wid] = ss; }
    __syncthreads();
    if (threadIdx.x == 0) {
        s = 0.f; ss = 0.f;
        #pragma unroll
        for (int w = 0; w < 8; w++) { s += sh[w]; ss += sh[8 + w]; }
        pstats[blockIdx.x * 2 + 0] = s;
        pstats[blockIdx.x * 2 + 1] = ss;
    }
}

// Normalize + transpose with fused stats finalize. Tile 32c x 128n.
__global__ void __launch_bounds__(256)
gn_transpose_kernel(const float* __restrict__ x, const float* __restrict__ pstats,
                    const float* __restrict__ scale, const float* __restrict__ bias,
                    bf16* __restrict__ hnT)
{
    __shared__ float tile[32 * 132];
    __shared__ float sstat[4];               // mean,rstd for the 2 groups
    const int n0 = blockIdx.x * 128;
    const int c0 = blockIdx.y * 32;
    const int b  = blockIdx.z;
    const float* xb = x + (size_t)b * CH * NPIX;
    bf16* hb = hnT + (size_t)b * NPIX * CH;
    const int tid = threadIdx.x;

    if (tid < 2) {                            // finalize stats for groups g0,g0+1
        int g = b * NGRP + (c0 >> 4) + tid;
        float s = 0.f, ss = 0.f;
        #pragma unroll
        for (int j = 0; j < 8; j++) {
            s  += pstats[(g * 8 + j) * 2 + 0];
            ss += pstats[(g * 8 + j) * 2 + 1];
        }
        const float NPG = (float)((CH / NGRP) * NPIX);
        float mean = s / NPG;
        float var  = ss / NPG - mean * mean;
        sstat[tid * 2 + 0] = mean;
        sstat[tid * 2 + 1] = rsqrtf(var + 1e-6f);
    }
    __syncthreads();

    #pragma unroll
    for (int r = 0; r < 4; r++) {
        int idx = r * 256 + tid;
        int ci  = idx >> 5;
        int n4  = idx & 31;
        int c   = c0 + ci;
        float mean = sstat[(ci >> 4) * 2 + 0];
        float rstd = sstat[(ci >> 4) * 2 + 1];
        float sc = scale[c], bi = bias[c];
        float4 v = *(const float4*)&xb[(size_t)c * NPIX + n0 + n4 * 4];
        float* tp = &tile[ci * 132 + n4 * 4];
        tp[0] = (v.x - mean) * rstd * sc + bi;
        tp[1] = (v.y - mean) * rstd * sc + bi;
        tp[2] = (v.z - mean) * rstd * sc + bi;
        tp[3] = (v.w - mean) * rstd * sc + bi;
    }
    __syncthreads();
    #pragma unroll
    for (int r = 0; r < 2; r++) {
        int idx = r * 256 + tid;
        int ni  = idx >> 2;
        int cq  = idx & 3;
        uint32_t w[4];
        #pragma unroll
        for (int j = 0; j < 4; j++) {
            float lo = tile[(cq * 8 + 2 * j)     * 132 + ni];
            float hi = tile[(cq * 8 + 2 * j + 1) * 132 + ni];
            __nv_bfloat162 p;
            p.x = __float2bfloat16_rn(lo);
            p.y = __float2bfloat16_rn(hi);
            w[j] = *(uint32_t*)&p;
        }
        *(uint4*)&hb[(size_t)(n0 + ni) * CH + c0 + cq * 8] = *(uint4*)w;
    }
}

// ---------------------------------------------------------------------------
// TMA-fed bf16 GEMM (R14 core). BM=BN=128, BK=64 (SW128), 3 stages,
// 8 warps (4x2), warp tile 32x64, m16n8k16, full/empty mbarrier pipeline.
// BIAS_MODE: 0 none, 1 bias[m], 2 bias[n], 3 softmax epi (exp + psum),
//            4 rowscale: bias = psum; epilogue computes inv = 1/sum(psum[row]).
// BA/BB: operand batched.
// ---------------------------------------------------------------------------
static constexpr int TILE_B  = 128 * 128;
static constexpr int STAGE_B = 2 * TILE_B;
static constexpr int GSMEM   = 1024 + 3 * STAGE_B + 128;

template <int BIAS_MODE, bool RES, bool OUT_BF, bool BA, bool BB>
__global__ void __launch_bounds__(256)
tgemm(int nt, int kAo, int kBo,
      const __grid_constant__ CUtensorMap tmA,
      const __grid_constant__ CUtensorMap tmB,
      void* __restrict__ Cvp, int ldc, size_t sC,
      const float* __restrict__ bias,
      const float* __restrict__ res, size_t sR,
      float alpha)
{
    extern __shared__ char smraw[];
    const uint32_t sb = smem_u32(smraw);
    const uint32_t tb = (sb + 1023) & ~1023u;
    const uint32_t fullb  = tb + 3 * STAGE_B;
    const uint32_t emptyb = fullb + 24;

    const int bz = blockIdx.z;
    const int m0 = blockIdx.y * 128;
    const int n0 = blockIdx.x * 128;
    const int tid  = threadIdx.x;
    const int lane = tid & 31;
    const int wid  = tid >> 5;
    const int wm   = wid >> 1;
    const int wn   = wid & 1;
    const int grp  = lane >> 2;
    const int tig  = lane & 3;
    const int lrow = lane & 15;
    const int lkb  = (lane >> 4) << 4;
    const int zA = BA ? bz : 0;
    const int zB = BB ? bz : 0;

    if (RES) res += sR * bz;

    if (tid == 0) {
        #pragma unroll
        for (int s = 0; s < 3; s++) {
            mbar_init(fullb  + 8 * s, 1);
            mbar_init(emptyb + 8 * s, 8);
        }
    }
    __syncthreads();

    if (tid == 0) {
        #pragma unroll
        for (int s = 0; s < 3; s++) {
            mbar_expect_tx(fullb + 8 * s, STAGE_B);
            tma_load3d(tb + s * STAGE_B,          &tmA, kAo + s * 64, m0, zA, fullb + 8 * s);
            tma_load3d(tb + s * STAGE_B + TILE_B, &tmB, kBo + s * 64, n0, zB, fullb + 8 * s);
        }
    }

    float acc[2][8][4];
    #pragma unroll
    for (int mi = 0; mi < 2; mi++)
        #pragma unroll
        for (int ni = 0; ni < 8; ni++)
            #pragma unroll
            for (int r = 0; r < 4; r++)
                acc[mi][ni][r] = 0.f;

    for (int t = 0; t < nt; t++) {
        const int tp = t / 3;
        const int st = t - tp * 3;
        const uint32_t ph = tp & 1;
        mbar_wait(fullb + 8 * st, ph);
        const uint32_t As = tb + st * STAGE_B;
        const uint32_t Bs = As + TILE_B;

        #pragma unroll
        for (int ks = 0; ks < 4; ks++) {
            const uint32_t colb = ks * 32 + lkb;
            uint32_t af[2][4];
            #pragma unroll
            for (int mi = 0; mi < 2; mi++) {
                int row = wm * 32 + mi * 16 + lrow;
                ldsm_x4(af[mi][0], af[mi][1], af[mi][2], af[mi][3],
                        As + swz(row * 128 + colb));
            }
            uint32_t bfr[8][2];
            #pragma unroll
            for (int nb = 0; nb < 4; nb++) {
                int row = wn * 64 + nb * 16 + lrow;
                uint32_t r0, r1, r2, r3;
                ldsm_x4(r0, r1, r2, r3, Bs + swz(row * 128 + colb));
                bfr[nb * 2][0] = r0; bfr[nb * 2][1] = r2;
                bfr[nb * 2 + 1][0] = r1; bfr[nb * 2 + 1][1] = r3;
            }
            #pragma unroll
            for (int mi = 0; mi < 2; mi++)
                #pragma unroll
                for (int ni = 0; ni < 8; ni++)
                    mma_bf16(acc[mi][ni], af[mi], bfr[ni]);
        }
        if (lane == 0) mbar_arrive(emptyb + 8 * st);
        if (tid == 0 && t + 3 < nt) {
            mbar_wait(emptyb + 8 * st, ph);
            mbar_expect_tx(fullb + 8 * st, STAGE_B);
            tma_load3d(tb + st * STAGE_B,          &tmA, kAo + (t + 3) * 64, m0, zA, fullb + 8 * st);
            tma_load3d(tb + st * STAGE_B + TILE_B, &tmB, kBo + (t + 3) * 64, n0, zB, fullb + 8 * st);
        }
    }

    // -------------------- epilogue --------------------
    float* rows_s = (float*)smraw;
    if (BIAS_MODE == 3) {
        __syncthreads();
        if (tid < 128) rows_s[tid] = 0.f;
        __syncthreads();
    }

    #pragma unroll
    for (int mi = 0; mi < 2; mi++) {
        int lr0 = wm * 32 + mi * 16 + grp;
        int r0 = m0 + lr0;
        int r1 = r0 + 8;
        float brow0 = (BIAS_MODE == 1) ? bias[r0] : 0.f;
        float brow1 = (BIAS_MODE == 1) ? bias[r1] : 0.f;
        float sc0 = 1.f, sc1 = 1.f;
        if (BIAS_MODE == 4) {
            // fixed-order sum of the 32 psum partials -> deterministic inv
            const float* p0 = bias + ((size_t)bz * NPIX + r0) * JT;
            const float* p1 = bias + ((size_t)bz * NPIX + r1) * JT;
            float s0 = 0.f, s1 = 0.f;
            #pragma unroll
            for (int j = 0; j < JT; j++) { s0 += p0[j]; s1 += p1[j]; }
            sc0 = 1.f / s0;
            sc1 = 1.f / s1;
        }
        float rsum0 = 0.f, rsum1 = 0.f;
        #pragma unroll
        for (int ni = 0; ni < 8; ni++) {
            int c = n0 + wn * 64 + ni * 8 + tig * 2;
            float v0 = acc[mi][ni][0] * alpha;
            float v1 = acc[mi][ni][1] * alpha;
            float v2 = acc[mi][ni][2] * alpha;
            float v3 = acc[mi][ni][3] * alpha;
            if (BIAS_MODE == 1) { v0 += brow0; v1 += brow0; v2 += brow1; v3 += brow1; }
            if (BIAS_MODE == 2) {
                float bc0 = bias[c], bc1 = bias[c + 1];
                v0 += bc0; v1 += bc1; v2 += bc0; v3 += bc1;
            }
            if (BIAS_MODE == 3) {
                v0 = __expf(v0); v1 = __expf(v1);
                v2 = __expf(v2); v3 = __expf(v3);
                rsum0 += v0 + v1; rsum1 += v2 + v3;
            }
            if (BIAS_MODE == 4) { v0 *= sc0; v1 *= sc0; v2 *= sc1; v3 *= sc1; }
            if (RES) {
                v0 += res[(size_t)r0 * ldc + c];
                v1 += res[(size_t)r0 * ldc + c + 1];
                v2 += res[(size_t)r1 * ldc + c];
                v3 += res[(size_t)r1 * ldc + c + 1];
            }
            if (OUT_BF) {
                bf16* Cp = (bf16*)Cvp + sC * bz;
                __nv_bfloat162 w0, w1;
                w0.x = __float2bfloat16_rn(v0); w0.y = __float2bfloat16_rn(v1);
                w1.x = __float2bfloat16_rn(v2); w1.y = __float2bfloat16_rn(v3);
                *(__nv_bfloat162*)&Cp[(size_t)r0 * ldc + c] = w0;
                *(__nv_bfloat162*)&Cp[(size_t)r1 * ldc + c] = w1;
            } else {
                float* Cp = (float*)Cvp + sC * bz;
                *(float2*)&Cp[(size_t)r0 * ldc + c] = make_float2(v0, v1);
                *(float2*)&Cp[(size_t)r1 * ldc + c] = make_float2(v2, v3);
            }
        }
        if (BIAS_MODE == 3) {
            rsum0 += __shfl_xor_sync(0xffffffffu, rsum0, 1);
            rsum0 += __shfl_xor_sync(0xffffffffu, rsum0, 2);
            rsum1 += __shfl_xor_sync(0xffffffffu, rsum1, 1);
            rsum1 += __shfl_xor_sync(0xffffffffu, rsum1, 2);
            if (tig == 0) {
                atomicAdd(&rows_s[lr0], rsum0);       // 2 commutative adds/row
                atomicAdd(&rows_s[lr0 + 8], rsum1);
            }
        }
    }
    if (BIAS_MODE == 3) {
        __syncthreads();
        if (tid < 128) {
            float* psum = (float*)bias;
            psum[((size_t)bz * NPIX + m0 + tid) * JT + blockIdx.x] = rows_s[tid];
        }
    }
}

// ---------------------------------------------------------------------------
// Launch
// ---------------------------------------------------------------------------
typedef CUresult (*EncodeFn)(CUtensorMap*, CUtensorMapDataType, cuuint32_t, void*,
                             const cuuint64_t*, const cuuint64_t*, const cuuint32_t*,
                             const cuuint32_t*, CUtensorMapInterleave, CUtensorMapSwizzle,
                             CUtensorMapL2promotion, CUtensorMapFloatOOBfill);

static void encode3d(EncodeFn fn, CUtensorMap* tm, void* ptr,
                     uint64_t d0, uint64_t d1, uint64_t d2,
                     uint64_t s1_bytes, uint64_t s2_bytes)
{
    cuuint64_t dims[3]    = {d0, d1, d2};
    cuuint64_t strides[2] = {s1_bytes, s2_bytes};
    cuuint32_t box[3]     = {64, 128, 1};
    cuuint32_t es[3]      = {1, 1, 1};
    fn(tm, CU_TENSOR_MAP_DATA_TYPE_BFLOAT16, 3, ptr, dims, strides, box, es,
       CU_TENSOR_MAP_INTERLEAVE_NONE, CU_TENSOR_MAP_SWIZZLE_128B,
       CU_TENSOR_MAP_L2_PROMOTION_L2_128B, CU_TENSOR_MAP_FLOAT_OOB_FILL_NONE);
}

extern "C" void kernel_launch(void* const* d_in, const int* in_sizes, int n_in,
                              void* d_out, int out_size)
{
    const float* x        = (const float*)d_in[0];
    const float* gn_scale = (const float*)d_in[1];
    const float* gn_bias  = (const float*)d_in[2];
    const float* wq       = (const float*)d_in[3];
    const float* bq       = (const float*)d_in[4];
    const float* wk       = (const float*)d_in[5];
    const float* bk       = (const float*)d_in[6];
    const float* wv       = (const float*)d_in[7];
    const float* bv       = (const float*)d_in[8];
    const float* wp       = (const float*)d_in[9];
    const float* bp       = (const float*)d_in[10];
    float* out            = (float*)d_out;

    static bf16 *hnT = nullptr, *qkT, *v, *probs, *oT, *rwqk, *rwv, *rwp;
    static float *pstats, *bqk, *psum;
    static CUtensorMap tmHN, tmWQK, tmWV, tmWP, tmV, tmP, tmO, tmQK;
    if (!hnT) {
        cudaGetSymbolAddress((void**)&hnT,  g_hn);
        cudaGetSymbolAddress((void**)&qkT,  g_qk);
        cudaGetSymbolAddress((void**)&v,    g_v);
        cudaGetSymbolAddress((void**)&probs,g_p);
        cudaGetSymbolAddress((void**)&oT,   g_o);
        cudaGetSymbolAddress((void**)&rwqk, g_wqk);
        cudaGetSymbolAddress((void**)&rwv,  g_wv);
        cudaGetSymbolAddress((void**)&rwp,  g_wp);
        cudaGetSymbolAddress((void**)&bqk,  g_bqk);
        cudaGetSymbolAddress((void**)&pstats, g_pstats);
        cudaGetSymbolAddress((void**)&psum, g_psum);

        void* fp = nullptr;
        cudaDriverEntryPointQueryResult qr;
        cudaGetDriverEntryPoint("cuTensorMapEncodeTiled", &fp, cudaEnableDefault, &qr);
        EncodeFn enc = (EncodeFn)fp;

        const uint64_t sCNb = (uint64_t)CH * NPIX * 2;
        const uint64_t sNNb = (uint64_t)NPIX * NPIX * 2;
        const uint64_t sQKb = (uint64_t)NPIX * 2 * CH * 2;
        encode3d(enc, &tmHN,  hnT,  CH,     NPIX, BSZ, CH * 2,     sCNb);
        encode3d(enc, &tmWQK, rwqk, CH,     1024, 1,   CH * 2,     (uint64_t)1024 * CH * 2);
        encode3d(enc, &tmWV,  rwv,  CH,     CH,   1,   CH * 2,     (uint64_t)CH * CH * 2);
        encode3d(enc, &tmWP,  rwp,  CH,     CH,   1,   CH * 2,     (uint64_t)CH * CH * 2);
        encode3d(enc, &tmV,   v,    NPIX,   CH,   BSZ, NPIX * 2,   sCNb);
        encode3d(enc, &tmP,   probs,NPIX,   NPIX, BSZ, NPIX * 2,   sNNb);
        encode3d(enc, &tmO,   oT,   CH,     NPIX, BSZ, CH * 2,     sCNb);
        encode3d(enc, &tmQK,  qkT,  2 * CH, NPIX, BSZ, 2 * CH * 2, sQKb);

        cudaFuncSetAttribute(tgemm<2, false, true,  true,  false>,
                             cudaFuncAttributeMaxDynamicSharedMemorySize, GSMEM);
        cudaFuncSetAttribute(tgemm<1, false, true,  false, true >,
                             cudaFuncAttributeMaxDynamicSharedMemorySize, GSMEM);
        cudaFuncSetAttribute(tgemm<3, false, true,  true,  true >,
                             cudaFuncAttributeMaxDynamicSharedMemorySize, GSMEM);
        cudaFuncSetAttribute(tgemm<4, false, true,  true,  true >,
                             cudaFuncAttributeMaxDynamicSharedMemorySize, GSMEM);
        cudaFuncSetAttribute(tgemm<1, true,  false, false, true >,
                             cudaFuncAttributeMaxDynamicSharedMemorySize, GSMEM);
    }

    const size_t sCN = (size_t)CH * NPIX;
    const size_t sNN = (size_t)NPIX * NPIX;
    const size_t sQK = (size_t)NPIX * 2 * CH;
    const float inv_sqrt_c = 0.044194173824159216f;

    round_weights_kernel<<<4 * CH * CH / 256, 256>>>(wq, wk, wv, wp, rwqk, rwv, rwp,
                                                     bq, bk, bqk);
    gn_stats1_kernel<<<BSZ * NGRP * 8, 256>>>(x, pstats);
    gn_transpose_kernel<<<dim3(NPIX / 128, CH / 32, BSZ), 256>>>(x, pstats, gn_scale,
                                                                 gn_bias, hnT);

    // qkT = hnT . Wqk^T + bqk   (M=4096, N=1024, K=512)
    tgemm<2, false, true, true, false><<<dim3(8, 32, BSZ), 256, GSMEM>>>(
        8, 0, 0, tmHN, tmWQK, qkT, 2 * CH, sQK, bqk, nullptr, 0, 1.f);

    // v = Wv . hnT^T + bv   (M=512, N=4096, K=512)
    tgemm<1, false, true, false, true><<<dim3(32, 4, BSZ), 256, GSMEM>>>(
        8, 0, 0, tmWV, tmHN, v, NPIX, sCN, bv, nullptr, 0, 1.f);

    // p~ = exp(alpha * q . k^T)   (M=N=4096, K=512)
    tgemm<3, false, true, true, true><<<dim3(32, 32, BSZ), 256, GSMEM>>>(
        8, 0, 512, tmQK, tmQK, probs, NPIX, sNN, psum, nullptr, 0, inv_sqrt_c);

    // oT = diag(1/rowsum) . p~ . v^T   (M=4096, N=512, K=4096); inv fused in epi
    tgemm<4, false, true, true, true><<<dim3(4, 32, BSZ), 256, GSMEM>>>(
        64, 0, 0, tmP, tmV, oT, CH, sCN, psum, nullptr, 0, 1.f);

    // out = Wp . oT^T + bp + x   (M=512, N=4096, K=512)
    tgemm<1, true, false, false, true><<<dim3(32, 4, BSZ), 256, GSMEM>>>(
        8, 0, 0, tmWP, tmO, out, NPIX, sCN, bp, x, sCN, 1.f);
}

// round 17
// speedup vs baseline: 1.0299x; 1.0023x over previous
#include <cuda_runtime.h>
#include <cuda.h>
#include <cuda_bf16.h>
#include <math.h>
#include <stdint.h>

// ---------------------------------------------------------------------------
// AttentionBlock, bf16 mma.m16n8k16 + TMA (R16 core) + stream-forked overlap:
// round_weights || gn_stats/transpose, and QKV-GEMM || V-GEMM, fork/join via
// events (graph-capture-legal).
// D[M,N] = alpha * A[M,K] . B[N,K]^T, bf16 in, fp32 accum.
// ---------------------------------------------------------------------------

static constexpr int BSZ  = 2;
static constexpr int CH   = 512;
static constexpr int NPIX = 4096;
static constexpr int NGRP = 32;
static constexpr int JT   = NPIX / 128;   // 32 j-tiles per row

typedef __nv_bfloat16 bf16;

__device__ bf16  g_hn[(size_t)BSZ * NPIX * CH];          // hnT [b][n][c]
__device__ bf16  g_qk[(size_t)BSZ * NPIX * 2 * CH];      // qkT [b][n][1024]
__device__ bf16  g_v [(size_t)BSZ * CH * NPIX];          // v   [b][c][n]
__device__ bf16  g_o [(size_t)BSZ * NPIX * CH];          // oT  [b][n][c]
__device__ bf16  g_p [(size_t)BSZ * NPIX * NPIX];        // p~ = exp(logit)
__device__ float g_psum[(size_t)BSZ * NPIX * JT];
__device__ bf16  g_wqk[2 * CH * CH];
__device__ bf16  g_wv[CH * CH];
__device__ bf16  g_wp[CH * CH];
__device__ float g_bqk[2 * CH];
__device__ float g_pstats[BSZ * NGRP * 8 * 2];           // phase-1 partials

// ---------------------------------------------------------------------------
__device__ __forceinline__ uint32_t smem_u32(const void* p) {
    return (uint32_t)__cvta_generic_to_shared(p);
}
__device__ __forceinline__ uint32_t swz(uint32_t off) {
    return off ^ ((off >> 3) & 0x70);
}
__device__ __forceinline__ void mbar_init(uint32_t a, uint32_t cnt) {
    asm volatile("mbarrier.init.shared.b64 [%0], %1;" :: "r"(a), "r"(cnt) : "memory");
}
__device__ __forceinline__ void mbar_arrive(uint32_t a) {
    asm volatile("mbarrier.arrive.shared.b64 _, [%0];" :: "r"(a) : "memory");
}
__device__ __forceinline__ void mbar_expect_tx(uint32_t a, uint32_t bytes) {
    asm volatile("mbarrier.arrive.expect_tx.shared.b64 _, [%0], %1;"
                 :: "r"(a), "r"(bytes) : "memory");
}
__device__ __forceinline__ void mbar_wait(uint32_t a, uint32_t parity) {
    asm volatile(
        "{\n\t.reg .pred P;\n\t"
        "W_%=:\n\t"
        "mbarrier.try_wait.parity.acquire.cta.shared::cta.b64 P, [%0], %1, 0x989680;\n\t"
        "@!P bra W_%=;\n\t}"
        :: "r"(a), "r"(parity) : "memory");
}
__device__ __forceinline__ void tma_load3d(uint32_t dst, const CUtensorMap* tm,
                                           int x, int y, int z, uint32_t mbar) {
    asm volatile(
        "cp.async.bulk.tensor.3d.shared::cta.global.tile.mbarrier::complete_tx::bytes "
        "[%0], [%1, {%2, %3, %4}], [%5];"
        :: "r"(dst), "l"(tm), "r"(x), "r"(y), "r"(z), "r"(mbar) : "memory");
}
__device__ __forceinline__ void ldsm_x4(uint32_t& r0, uint32_t& r1,
                                        uint32_t& r2, uint32_t& r3, uint32_t a) {
    asm volatile("ldmatrix.sync.aligned.m8n8.x4.shared.b16 {%0,%1,%2,%3}, [%4];"
                 : "=r"(r0), "=r"(r1), "=r"(r2), "=r"(r3) : "r"(a));
}
__device__ __forceinline__ void mma_bf16(float* c, const uint32_t* a, const uint32_t* b) {
    asm volatile(
        "mma.sync.aligned.m16n8k16.row.col.f32.bf16.bf16.f32 "
        "{%0,%1,%2,%3}, {%4,%5,%6,%7}, {%8,%9}, {%0,%1,%2,%3};"
        : "+f"(c[0]), "+f"(c[1]), "+f"(c[2]), "+f"(c[3])
        : "r"(a[0]), "r"(a[1]), "r"(a[2]), "r"(a[3]), "r"(b[0]), "r"(b[1]));
}

// ---------------------------------------------------------------------------
// prep: weights -> bf16 + bias concat (fused)
// ---------------------------------------------------------------------------
__global__ void round_weights_kernel(const float* __restrict__ a, const float* __restrict__ b,
                                     const float* __restrict__ c, const float* __restrict__ d,
                                     bf16* __restrict__ wqk, bf16* __restrict__ wv,
                                     bf16* __restrict__ wp,
                                     const float* __restrict__ bq,
                                     const float* __restrict__ bk,
                                     float* __restrict__ bqk)
{
    int i = blockIdx.x * blockDim.x + threadIdx.x;
    int w = i >> 18;
    int off = i & ((1 << 18) - 1);
    const float* src = (w == 0) ? a : (w == 1) ? b : (w == 2) ? c : d;
    bf16* dst = (w == 0) ? wqk : (w == 1) ? (wqk + CH * CH) : (w == 2) ? wv : wp;
    dst[off] = __float2bfloat16_rn(src[off]);
    if (i < 2 * CH) bqk[i] = (i < CH) ? bq[i] : bk[i - CH];
}

// GroupNorm stats phase 1: 8 blocks per (b,g), partial sums.
__global__ void gn_stats1_kernel(const float* __restrict__ x, float* __restrict__ pstats)
{
    const int CHUNK = 8192;
    const float4* xp = (const float4*)(x + (size_t)blockIdx.x * CHUNK);
    float s = 0.f, ss = 0.f;
    #pragma unroll
    for (int i = 0; i < CHUNK / 4 / 256; i++) {
        float4 v = xp[i * 256 + threadIdx.x];
        s  += v.x + v.y + v.z + v.w;
        ss += v.x * v.x + v.y * v.y + v.z * v.z + v.w * v.w;
    }
    __shared__ float sh[16];
    #pragma unroll
    for (int o = 16; o; o >>= 1) {
        s  += __shfl_xor_sync(0xffffffffu, s,  o);
        ss += __shfl_xor_sync(0xffffffffu, ss, o);
    }
    int wid = threadIdx.x >> 5, lid = threadIdx.x & 31;
    if (lid == 0) { sh[wid] = s; sh[8 + wid] = ss; }
    __syncthreads();
    if (threadIdx.x == 0) {
        s = 0.f; ss = 0.f;
        #pragma unroll
        for (int w = 0; w < 8; w++) { s += sh[w]; ss += sh[8 + w]; }
        pstats[blockIdx.x * 2 + 0] = s;
        pstats[blockIdx.x * 2 + 1] = ss;
    }
}

// Normalize + transpose with fused stats finalize. Tile 32c x 128n.
__global__ void __launch_bounds__(256)
gn_transpose_kernel(const float* __restrict__ x, const float* __restrict__ pstats,
                    const float* __restrict__ scale, const float* __restrict__ bias,
                    bf16* __restrict__ hnT)
{
    __shared__ float tile[32 * 132];
    __shared__ float sstat[4];
    const int n0 = blockIdx.x * 128;
    const int c0 = blockIdx.y * 32;
    const int b  = blockIdx.z;
    const float* xb = x + (size_t)b * CH * NPIX;
    bf16* hb = hnT + (size_t)b * NPIX * CH;
    const int tid = threadIdx.x;

    if (tid < 2) {
        int g = b * NGRP + (c0 >> 4) + tid;
        float s = 0.f, ss = 0.f;
        #pragma unroll
        for (int j = 0; j < 8; j++) {
            s  += pstats[(g * 8 + j) * 2 + 0];
            ss += pstats[(g * 8 + j) * 2 + 1];
        }
        const float NPG = (float)((CH / NGRP) * NPIX);
        float mean = s / NPG;
        float var  = ss / NPG - mean * mean;
        sstat[tid * 2 + 0] = mean;
        sstat[tid * 2 + 1] = rsqrtf(var + 1e-6f);
    }
    __syncthreads();

    #pragma unroll
    for (int r = 0; r < 4; r++) {
        int idx = r * 256 + tid;
        int ci  = idx >> 5;
        int n4  = idx & 31;
        int c   = c0 + ci;
        float mean = sstat[(ci >> 4) * 2 + 0];
        float rstd = sstat[(ci >> 4) * 2 + 1];
        float sc = scale[c], bi = bias[c];
        float4 v = *(const float4*)&xb[(size_t)c * NPIX + n0 + n4 * 4];
        float* tp = &tile[ci * 132 + n4 * 4];
        tp[0] = (v.x - mean) * rstd * sc + bi;
        tp[1] = (v.y - mean) * rstd * sc + bi;
        tp[2] = (v.z - mean) * rstd * sc + bi;
        tp[3] = (v.w - mean) * rstd * sc + bi;
    }
    __syncthreads();
    #pragma unroll
    for (int r = 0; r < 2; r++) {
        int idx = r * 256 + tid;
        int ni  = idx >> 2;
        int cq  = idx & 3;
        uint32_t w[4];
        #pragma unroll
        for (int j = 0; j < 4; j++) {
            float lo = tile[(cq * 8 + 2 * j)     * 132 + ni];
            float hi = tile[(cq * 8 + 2 * j + 1) * 132 + ni];
            __nv_bfloat162 p;
            p.x = __float2bfloat16_rn(lo);
            p.y = __float2bfloat16_rn(hi);
            w[j] = *(uint32_t*)&p;
        }
        *(uint4*)&hb[(size_t)(n0 + ni) * CH + c0 + cq * 8] = *(uint4*)w;
    }
}

// ---------------------------------------------------------------------------
// TMA-fed bf16 GEMM (R14/R16 core). BM=BN=128, BK=64 (SW128), 3 stages,
// 8 warps (4x2), warp tile 32x64, m16n8k16, full/empty mbarrier pipeline.
// BIAS_MODE: 0 none, 1 bias[m], 2 bias[n], 3 softmax epi (exp + psum),
//            4 rowscale: bias = psum; epilogue computes inv = 1/sum(psum[row]).
// BA/BB: operand batched.
// ---------------------------------------------------------------------------
static constexpr int TILE_B  = 128 * 128;
static constexpr int STAGE_B = 2 * TILE_B;
static constexpr int GSMEM   = 1024 + 3 * STAGE_B + 128;

template <int BIAS_MODE, bool RES, bool OUT_BF, bool BA, bool BB>
__global__ void __launch_bounds__(256)
tgemm(int nt, int kAo, int kBo,
      const __grid_constant__ CUtensorMap tmA,
      const __grid_constant__ CUtensorMap tmB,
      void* __restrict__ Cvp, int ldc, size_t sC,
      const float* __restrict__ bias,
      const float* __restrict__ res, size_t sR,
      float alpha)
{
    extern __shared__ char smraw[];
    const uint32_t sb = smem_u32(smraw);
    const uint32_t tb = (sb + 1023) & ~1023u;
    const uint32_t fullb  = tb + 3 * STAGE_B;
    const uint32_t emptyb = fullb + 24;

    const int bz = blockIdx.z;
    const int m0 = blockIdx.y * 128;
    const int n0 = blockIdx.x * 128;
    const int tid  = threadIdx.x;
    const int lane = tid & 31;
    const int wid  = tid >> 5;
    const int wm   = wid >> 1;
    const int wn   = wid & 1;
    const int grp  = lane >> 2;
    const int tig  = lane & 3;
    const int lrow = lane & 15;
    const int lkb  = (lane >> 4) << 4;
    const int zA = BA ? bz : 0;
    const int zB = BB ? bz : 0;

    if (RES) res += sR * bz;

    if (tid == 0) {
        #pragma unroll
        for (int s = 0; s < 3; s++) {
            mbar_init(fullb  + 8 * s, 1);
            mbar_init(emptyb + 8 * s, 8);
        }
    }
    __syncthreads();

    if (tid == 0) {
        #pragma unroll
        for (int s = 0; s < 3; s++) {
            mbar_expect_tx(fullb + 8 * s, STAGE_B);
            tma_load3d(tb + s * STAGE_B,          &tmA, kAo + s * 64, m0, zA, fullb + 8 * s);
            tma_load3d(tb + s * STAGE_B + TILE_B, &tmB, kBo + s * 64, n0, zB, fullb + 8 * s);
        }
    }

    float acc[2][8][4];
    #pragma unroll
    for (int mi = 0; mi < 2; mi++)
        #pragma unroll
        for (int ni = 0; ni < 8; ni++)
            #pragma unroll
            for (int r = 0; r < 4; r++)
                acc[mi][ni][r] = 0.f;

    for (int t = 0; t < nt; t++) {
        const int tp = t / 3;
        const int st = t - tp * 3;
        const uint32_t ph = tp & 1;
        mbar_wait(fullb + 8 * st, ph);
        const uint32_t As = tb + st * STAGE_B;
        const uint32_t Bs = As + TILE_B;

        #pragma unroll
        for (int ks = 0; ks < 4; ks++) {
            const uint32_t colb = ks * 32 + lkb;
            uint32_t af[2][4];
            #pragma unroll
            for (int mi = 0; mi < 2; mi++) {
                int row = wm * 32 + mi * 16 + lrow;
                ldsm_x4(af[mi][0], af[mi][1], af[mi][2], af[mi][3],
                        As + swz(row * 128 + colb));
            }
            uint32_t bfr[8][2];
            #pragma unroll
            for (int nb = 0; nb < 4; nb++) {
                int row = wn * 64 + nb * 16 + lrow;
                uint32_t r0, r1, r2, r3;
                ldsm_x4(r0, r1, r2, r3, Bs + swz(row * 128 + colb));
                bfr[nb * 2][0] = r0; bfr[nb * 2][1] = r2;
                bfr[nb * 2 + 1][0] = r1; bfr[nb * 2 + 1][1] = r3;
            }
            #pragma unroll
            for (int mi = 0; mi < 2; mi++)
                #pragma unroll
                for (int ni = 0; ni < 8; ni++)
                    mma_bf16(acc[mi][ni], af[mi], bfr[ni]);
        }
        if (lane == 0) mbar_arrive(emptyb + 8 * st);
        if (tid == 0 && t + 3 < nt) {
            mbar_wait(emptyb + 8 * st, ph);
            mbar_expect_tx(fullb + 8 * st, STAGE_B);
            tma_load3d(tb + st * STAGE_B,          &tmA, kAo + (t + 3) * 64, m0, zA, fullb + 8 * st);
            tma_load3d(tb + st * STAGE_B + TILE_B, &tmB, kBo + (t + 3) * 64, n0, zB, fullb + 8 * st);
        }
    }

    // -------------------- epilogue --------------------
    float* rows_s = (float*)smraw;
    if (BIAS_MODE == 3) {
        __syncthreads();
        if (tid < 128) rows_s[tid] = 0.f;
        __syncthreads();
    }

    #pragma unroll
    for (int mi = 0; mi < 2; mi++) {
        int lr0 = wm * 32 + mi * 16 + grp;
        int r0 = m0 + lr0;
        int r1 = r0 + 8;
        float brow0 = (BIAS_MODE == 1) ? bias[r0] : 0.f;
        float brow1 = (BIAS_MODE == 1) ? bias[r1] : 0.f;
        float sc0 = 1.f, sc1 = 1.f;
        if (BIAS_MODE == 4) {
            const float* p0 = bias + ((size_t)bz * NPIX + r0) * JT;
            const float* p1 = bias + ((size_t)bz * NPIX + r1) * JT;
            float s0 = 0.f, s1 = 0.f;
            #pragma unroll
            for (int j = 0; j < JT; j++) { s0 += p0[j]; s1 += p1[j]; }
            sc0 = 1.f / s0;
            sc1 = 1.f / s1;
        }
        float rsum0 = 0.f, rsum1 = 0.f;
        #pragma unroll
        for (int ni = 0; ni < 8; ni++) {
            int c = n0 + wn * 64 + ni * 8 + tig * 2;
            float v0 = acc[mi][ni][0] * alpha;
            float v1 = acc[mi][ni][1] * alpha;
            float v2 = acc[mi][ni][2] * alpha;
            float v3 = acc[mi][ni][3] * alpha;
            if (BIAS_MODE == 1) { v0 += brow0; v1 += brow0; v2 += brow1; v3 += brow1; }
            if (BIAS_MODE == 2) {
                float bc0 = bias[c], bc1 = bias[c + 1];
                v0 += bc0; v1 += bc1; v2 += bc0; v3 += bc1;
            }
            if (BIAS_MODE == 3) {
                v0 = __expf(v0); v1 = __expf(v1);
                v2 = __expf(v2); v3 = __expf(v3);
                rsum0 += v0 + v1; rsum1 += v2 + v3;
            }
            if (BIAS_MODE == 4) { v0 *= sc0; v1 *= sc0; v2 *= sc1; v3 *= sc1; }
            if (RES) {
                v0 += res[(size_t)r0 * ldc + c];
                v1 += res[(size_t)r0 * ldc + c + 1];
                v2 += res[(size_t)r1 * ldc + c];
                v3 += res[(size_t)r1 * ldc + c + 1];
            }
            if (OUT_BF) {
                bf16* Cp = (bf16*)Cvp + sC * bz;
                __nv_bfloat162 w0, w1;
                w0.x = __float2bfloat16_rn(v0); w0.y = __float2bfloat16_rn(v1);
                w1.x = __float2bfloat16_rn(v2); w1.y = __float2bfloat16_rn(v3);
                *(__nv_bfloat162*)&Cp[(size_t)r0 * ldc + c] = w0;
                *(__nv_bfloat162*)&Cp[(size_t)r1 * ldc + c] = w1;
            } else {
                float* Cp = (float*)Cvp + sC * bz;
                *(float2*)&Cp[(size_t)r0 * ldc + c] = make_float2(v0, v1);
                *(float2*)&Cp[(size_t)r1 * ldc + c] = make_float2(v2, v3);
            }
        }
        if (BIAS_MODE == 3) {
            rsum0 += __shfl_xor_sync(0xffffffffu, rsum0, 1);
            rsum0 += __shfl_xor_sync(0xffffffffu, rsum0, 2);
            rsum1 += __shfl_xor_sync(0xffffffffu, rsum1, 1);
            rsum1 += __shfl_xor_sync(0xffffffffu, rsum1, 2);
            if (tig == 0) {
                atomicAdd(&rows_s[lr0], rsum0);
                atomicAdd(&rows_s[lr0 + 8], rsum1);
            }
        }
    }
    if (BIAS_MODE == 3) {
        __syncthreads();
        if (tid < 128) {
            float* psum = (float*)bias;
            psum[((size_t)bz * NPIX + m0 + tid) * JT + blockIdx.x] = rows_s[tid];
        }
    }
}

// ---------------------------------------------------------------------------
// Launch
// ---------------------------------------------------------------------------
typedef CUresult (*EncodeFn)(CUtensorMap*, CUtensorMapDataType, cuuint32_t, void*,
                             const cuuint64_t*, const cuuint64_t*, const cuuint32_t*,
                             const cuuint32_t*, CUtensorMapInterleave, CUtensorMapSwizzle,
                             CUtensorMapL2promotion, CUtensorMapFloatOOBfill);

static void encode3d(EncodeFn fn, CUtensorMap* tm, void* ptr,
                     uint64_t d0, uint64_t d1, uint64_t d2,
                     uint64_t s1_bytes, uint64_t s2_bytes)
{
    cuuint64_t dims[3]    = {d0, d1, d2};
    cuuint64_t strides[2] = {s1_bytes, s2_bytes};
    cuuint32_t box[3]     = {64, 128, 1};
    cuuint32_t es[3]      = {1, 1, 1};
    fn(tm, CU_TENSOR_MAP_DATA_TYPE_BFLOAT16, 3, ptr, dims, strides, box, es,
       CU_TENSOR_MAP_INTERLEAVE_NONE, CU_TENSOR_MAP_SWIZZLE_128B,
       CU_TENSOR_MAP_L2_PROMOTION_L2_128B, CU_TENSOR_MAP_FLOAT_OOB_FILL_NONE);
}

extern "C" void kernel_launch(void* const* d_in, const int* in_sizes, int n_in,
                              void* d_out, int out_size)
{
    const float* x        = (const float*)d_in[0];
    const float* gn_scale = (const float*)d_in[1];
    const float* gn_bias  = (const float*)d_in[2];
    const float* wq       = (const float*)d_in[3];
    const float* bq       = (const float*)d_in[4];
    const float* wk       = (const float*)d_in[5];
    const float* bk       = (const float*)d_in[6];
    const float* wv       = (const float*)d_in[7];
    const float* bv       = (const float*)d_in[8];
    const float* wp       = (const float*)d_in[9];
    const float* bp       = (const float*)d_in[10];
    float* out            = (float*)d_out;

    static bf16 *hnT = nullptr, *qkT, *v, *probs, *oT, *rwqk, *rwv, *rwp;
    static float *pstats, *bqk, *psum;
    static CUtensorMap tmHN, tmWQK, tmWV, tmWP, tmV, tmP, tmO, tmQK;
    static cudaStream_t s1;
    static cudaEvent_t ev0, ev1, ev2, ev3;
    if (!hnT) {
        cudaGetSymbolAddress((void**)&hnT,  g_hn);
        cudaGetSymbolAddress((void**)&qkT,  g_qk);
        cudaGetSymbolAddress((void**)&v,    g_v);
        cudaGetSymbolAddress((void**)&probs,g_p);
        cudaGetSymbolAddress((void**)&oT,   g_o);
        cudaGetSymbolAddress((void**)&rwqk, g_wqk);
        cudaGetSymbolAddress((void**)&rwv,  g_wv);
        cudaGetSymbolAddress((void**)&rwp,  g_wp);
        cudaGetSymbolAddress((void**)&bqk,  g_bqk);
        cudaGetSymbolAddress((void**)&pstats, g_pstats);
        cudaGetSymbolAddress((void**)&psum, g_psum);

        cudaStreamCreateWithFlags(&s1, cudaStreamNonBlocking);
        cudaEventCreateWithFlags(&ev0, cudaEventDisableTiming);
        cudaEventCreateWithFlags(&ev1, cudaEventDisableTiming);
        cudaEventCreateWithFlags(&ev2, cudaEventDisableTiming);
        cudaEventCreateWithFlags(&ev3, cudaEventDisableTiming);

        void* fp = nullptr;
        cudaDriverEntryPointQueryResult qr;
        cudaGetDriverEntryPoint("cuTensorMapEncodeTiled", &fp, cudaEnableDefault, &qr);
        EncodeFn enc = (EncodeFn)fp;

        const uint64_t sCNb = (uint64_t)CH * NPIX * 2;
        const uint64_t sNNb = (uint64_t)NPIX * NPIX * 2;
        const uint64_t sQKb = (uint64_t)NPIX * 2 * CH * 2;
        encode3d(enc, &tmHN,  hnT,  CH,     NPIX, BSZ, CH * 2,     sCNb);
        encode3d(enc, &tmWQK, rwqk, CH,     1024, 1,   CH * 2,     (uint64_t)1024 * CH * 2);
        encode3d(enc, &tmWV,  rwv,  CH,     CH,   1,   CH * 2,     (uint64_t)CH * CH * 2);
        encode3d(enc, &tmWP,  rwp,  CH,     CH,   1,   CH * 2,     (uint64_t)CH * CH * 2);
        encode3d(enc, &tmV,   v,    NPIX,   CH,   BSZ, NPIX * 2,   sCNb);
        encode3d(enc, &tmP,   probs,NPIX,   NPIX, BSZ, NPIX * 2,   sNNb);
        encode3d(enc, &tmO,   oT,   CH,     NPIX, BSZ, CH * 2,     sCNb);
        encode3d(enc, &tmQK,  qkT,  2 * CH, NPIX, BSZ, 2 * CH * 2, sQKb);

        cudaFuncSetAttribute(tgemm<2, false, true,  true,  false>,
                             cudaFuncAttributeMaxDynamicSharedMemorySize, GSMEM);
        cudaFuncSetAttribute(tgemm<1, false, true,  false, true >,
                             cudaFuncAttributeMaxDynamicSharedMemorySize, GSMEM);
        cudaFuncSetAttribute(tgemm<3, false, true,  true,  true >,
                             cudaFuncAttributeMaxDynamicSharedMemorySize, GSMEM);
        cudaFuncSetAttribute(tgemm<4, false, true,  true,  true >,
                             cudaFuncAttributeMaxDynamicSharedMemorySize, GSMEM);
        cudaFuncSetAttribute(tgemm<1, true,  false, false, true >,
                             cudaFuncAttributeMaxDynamicSharedMemorySize, GSMEM);
    }

    const size_t sCN = (size_t)CH * NPIX;
    const size_t sNN = (size_t)NPIX * NPIX;
    const size_t sQK = (size_t)NPIX * 2 * CH;
    const float inv_sqrt_c = 0.044194173824159216f;

    // ---- fork 1: round_weights (s1)  ||  gn_stats1 + gn_transpose (main) ----
    cudaEventRecord(ev0, 0);
    cudaStreamWaitEvent(s1, ev0, 0);
    round_weights_kernel<<<4 * CH * CH / 256, 256, 0, s1>>>(wq, wk, wv, wp,
                                                            rwqk, rwv, rwp, bq, bk, bqk);
    gn_stats1_kernel<<<BSZ * NGRP * 8, 256>>>(x, pstats);
    gn_transpose_kernel<<<dim3(NPIX / 128, CH / 32, BSZ), 256>>>(x, pstats, gn_scale,
                                                                 gn_bias, hnT);
    cudaEventRecord(ev1, s1);
    cudaStreamWaitEvent(0, ev1, 0);     // main now has weights + hnT

    // ---- fork 2: QKV GEMM (main)  ||  V GEMM (s1) ----
    cudaEventRecord(ev2, 0);
    cudaStreamWaitEvent(s1, ev2, 0);
    // qkT = hnT . Wqk^T + bqk   (M=4096, N=1024, K=512)
    tgemm<2, false, true, true, false><<<dim3(8, 32, BSZ), 256, GSMEM>>>(
        8, 0, 0, tmHN, tmWQK, qkT, 2 * CH, sQK, bqk, nullptr, 0, 1.f);
    // v = Wv . hnT^T + bv   (M=512, N=4096, K=512)
    tgemm<1, false, true, false, true><<<dim3(32, 4, BSZ), 256, GSMEM, s1>>>(
        8, 0, 0, tmWV, tmHN, v, NPIX, sCN, bv, nullptr, 0, 1.f);
    cudaEventRecord(ev3, s1);
    cudaStreamWaitEvent(0, ev3, 0);     // join before AV needs v

    // p~ = exp(alpha * q . k^T)   (M=N=4096, K=512)
    tgemm<3, false, true, true, true><<<dim3(32, 32, BSZ), 256, GSMEM>>>(
        8, 0, 512, tmQK, tmQK, probs, NPIX, sNN, psum, nullptr, 0, inv_sqrt_c);

    // oT = diag(1/rowsum) . p~ . v^T   (M=4096, N=512, K=4096); inv fused in epi
    tgemm<4, false, true, true, true><<<dim3(4, 32, BSZ), 256, GSMEM>>>(
        64, 0, 0, tmP, tmV, oT, CH, sCN, psum, nullptr, 0, 1.f);

    // out = Wp . oT^T + bp + x   (M=512, N=4096, K=512)
    tgemm<1, true, false, false, true><<<dim3(32, 4, BSZ), 256, GSMEM>>>(
        8, 0, 0, tmWP, tmO, out, NPIX, sCN, bp, x, sCN, 1.f);
}